// round 14
// baseline (speedup 1.0000x reference)
#include <cuda_runtime.h>
#include <cuda_fp16.h>
#include <cuda.h>
#include <cstdint>

// ---------------- problem constants ----------------
#define HDIM   2048
#define SEQ    4096
#define NBATCH 8
#define MTOT   (NBATCH * SEQ)       // 32768
#define NLAYER 4

// ---------------- GEMM tile config ----------------
#define BM 128
#define BN 128
#define BK 64                        // 64 fp16 = 128 B rows (SW128)
#define KCHUNKS (HDIM / BK)          // 32
#define NSTAGES 3

// smem layout (bytes)
#define OFF_FULL(s)  ((s) * 8)       // 3 full barriers
#define OFF_EMPTY(s) (32 + (s) * 8)  // 3 empty barriers
#define OFF_BIAS     128             // BN floats = 512 B
#define OFF_STAGE    1024
#define OFF_A        0               // 128*128 B = 16384
#define OFF_B        16384           // 128*128 B = 16384
#define STAGE_BYTES  32768
#define SMEM_TOTAL   (OFF_STAGE + NSTAGES * STAGE_BYTES)   // 99328 -> 2 CTAs/SM

// ---------------- device scratch ----------------
__device__ __align__(1024) __half g_act[2ull * MTOT * HDIM];   // ping-pong fp16 activations
__device__ __align__(1024) __half g_w[(size_t)NLAYER * HDIM * HDIM];
__device__ int g_inv[(NLAYER - 1) * SEQ];

// ---------------- PTX helpers (baseline sm_103 only) ----------------
__device__ __forceinline__ uint32_t smem_u32(const void* p) {
    return (uint32_t)__cvta_generic_to_shared(p);
}

#define MBARRIER_INIT(addr, cnt) \
    asm volatile("mbarrier.init.shared.b64 [%0], %1;" :: "r"(addr), "r"(cnt) : "memory")

#define MBARRIER_ARRIVE(addr) \
    asm volatile("mbarrier.arrive.shared.b64 _, [%0];" :: "r"(addr) : "memory")

#define MBARRIER_EXPECT_TX(addr, bytes) \
    asm volatile("mbarrier.arrive.expect_tx.shared.b64 _, [%0], %1;" :: "r"(addr), "r"(bytes) : "memory")

#define MBARRIER_WAIT_PARITY(mbar_smem_addr, phase_parity) do { \
    uint32_t _mbar = (uint32_t)(mbar_smem_addr); \
    uint32_t _parity = (uint32_t)(phase_parity); \
    uint32_t _done_; \
    asm volatile( \
        "{\n\t.reg .pred p;\n\t" \
        "mbarrier.try_wait.parity.acquire.cta.shared::cta.b64 p, [%1], %2;\n\t" \
        "selp.b32 %0, 1, 0, p;\n\t}" \
        : "=r"(_done_) : "r"(_mbar), "r"(_parity) : "memory"); \
    if (!_done_) { \
        asm volatile( \
            "{\n\t.reg .pred P1;\n\t" \
            "WAIT_LOOP_%=:\n\t" \
            "mbarrier.try_wait.parity.acquire.cta.shared::cta.b64 P1, [%0], %1, 0x989680;\n\t" \
            "@P1 bra.uni WAIT_DONE_%=;\n\t" \
            "bra.uni WAIT_LOOP_%=;\n\t" \
            "WAIT_DONE_%=:\n\t}" \
            :: "r"(_mbar), "r"(_parity) : "memory"); \
    } \
} while (0)

#define TMA_LOAD_2D(dst, map, cx, cy, mbar) \
    asm volatile( \
        "cp.async.bulk.tensor.2d.shared::cta.global.tile.mbarrier::complete_tx::bytes " \
        "[%0], [%1, {%2, %3}], [%4];" \
        :: "r"((uint32_t)(dst)), "l"(map), "r"((int)(cx)), "r"((int)(cy)), "r"((uint32_t)(mbar)) \
        : "memory")

__device__ __forceinline__ void ldsm_x4(uint32_t* r, uint32_t addr) {
    asm volatile("ldmatrix.sync.aligned.m8n8.x4.shared.b16 {%0,%1,%2,%3}, [%4];"
        : "=r"(r[0]), "=r"(r[1]), "=r"(r[2]), "=r"(r[3]) : "r"(addr));
}

// D += A * B  (fp16 in, fp32 acc), m16n8k16
__device__ __forceinline__ void mma16816(float* d, const uint32_t* a, const uint32_t* b) {
    asm volatile("mma.sync.aligned.m16n8k16.row.col.f32.f16.f16.f32 "
        "{%0,%1,%2,%3}, {%4,%5,%6,%7}, {%8,%9}, {%0,%1,%2,%3};"
        : "+f"(d[0]), "+f"(d[1]), "+f"(d[2]), "+f"(d[3])
        : "r"(a[0]), "r"(a[1]), "r"(a[2]), "r"(a[3]), "r"(b[0]), "r"(b[1]));
}

// ---------------- pre-kernels ----------------
__global__ void convert_f16_kernel(const float* __restrict__ in,
                                   __half* __restrict__ out, int n4) {
    int stride = gridDim.x * blockDim.x;
    for (int i = blockIdx.x * blockDim.x + threadIdx.x; i < n4; i += stride) {
        float4 f = ((const float4*)in)[i];
        __half2 p0 = __floats2half2_rn(f.x, f.y);
        __half2 p1 = __floats2half2_rn(f.z, f.w);
        ((uint2*)out)[i] = make_uint2(*(uint32_t*)&p0, *(uint32_t*)&p1);
    }
}

__global__ void invperm_kernel(const int* __restrict__ perms, int* __restrict__ inv) {
    int i = blockIdx.x * blockDim.x + threadIdx.x;
    if (i < (NLAYER - 1) * SEQ) {
        int l = i / SEQ, s = i % SEQ;
        inv[l * SEQ + perms[i]] = s;
    }
}

// ---------------- main GEMM layer kernel ----------------
// C[BM x BN] = A_f16 . W_f16^T, +bias, scatter by invperm.
// 3-stage TMA pipeline; per-kk: all ldsm first, then MMAs; empty-arrive right
// after the last ldsm of a chunk; producer duty rotates across the 8 warps.
__global__ void __launch_bounds__(256, 2)
gemm_layer(const __grid_constant__ CUtensorMap mapA,
           const __grid_constant__ CUtensorMap mapB,
           const float* __restrict__ bias,
           const int* __restrict__ invperm,
           __half* __restrict__ outA,
           float* __restrict__ outF)
{
    extern __shared__ char smem[];
    const uint32_t sb = smem_u32(smem);
    const int tid  = threadIdx.x;
    const int wid  = tid >> 5;
    const int lane = tid & 31;
    const int warp_m = wid & 3;       // 4 warps along M (32 rows each)
    const int warp_n = wid >> 2;      // 2 warps along N (64 cols each)
    const int m0 = blockIdx.y * BM;
    const int n0 = blockIdx.x * BN;

    float* bias_s = (float*)(smem + OFF_BIAS);
    for (int i = tid; i < BN; i += 256) bias_s[i] = bias[n0 + i];

    if (tid == 0) {
#pragma unroll
        for (int s = 0; s < NSTAGES; ++s) {
            MBARRIER_INIT(sb + OFF_FULL(s), 1);
            MBARRIER_INIT(sb + OFF_EMPTY(s), 8);   // one arrival per warp
        }
    }
    __syncthreads();

    if (tid == 0) {
#pragma unroll
        for (int c = 0; c < NSTAGES; ++c) {
            MBARRIER_EXPECT_TX(sb + OFF_FULL(c), STAGE_BYTES);
            const uint32_t base = sb + OFF_STAGE + c * STAGE_BYTES;
            const int k0 = c * BK;
            TMA_LOAD_2D(base + OFF_A, &mapA, k0, m0, sb + OFF_FULL(c));
            TMA_LOAD_2D(base + OFF_B, &mapB, k0, n0, sb + OFF_FULL(c));
        }
    }

    // hoisted epilogue row gather (hide LDG latency behind the GEMM)
    const int r0 = m0 + warp_m * 32 + (lane >> 2);     // mt=0 row
    const int r1 = r0 + 8;
    const int r2 = r0 + 16;                            // mt=1 row
    const int r3 = r0 + 24;
    size_t q0, q1, q2, q3;
    if (invperm) {
        q0 = (size_t)((r0 & ~(SEQ - 1)) | invperm[r0 & (SEQ - 1)]);
        q1 = (size_t)((r1 & ~(SEQ - 1)) | invperm[r1 & (SEQ - 1)]);
        q2 = (size_t)((r2 & ~(SEQ - 1)) | invperm[r2 & (SEQ - 1)]);
        q3 = (size_t)((r3 & ~(SEQ - 1)) | invperm[r3 & (SEQ - 1)]);
    } else { q0 = (size_t)r0; q1 = (size_t)r1; q2 = (size_t)r2; q3 = (size_t)r3; }

    // per-lane ldmatrix geometry (SW128, 128B rows: phys_k = k ^ ((row&7)*16))
    const int rin = lane & 7;
    const int t8  = lane >> 3;                       // 8x8 tile index 0..3
    const int a_row_local = ((t8 & 1) << 3) + rin;   // A: tiles 0/1 rows, 2/3 k+16
    const int a_kadd      = (t8 >> 1) << 4;
    const int b_row_local = ((t8 >> 1) << 3) + rin;  // B: tiles 0/1 k, 2/3 n+8
    const int b_kadd      = (t8 & 1) << 4;
    const uint32_t ksw    = (uint32_t)(rin << 4);

    // invariant parts of ldsm addresses
    const uint32_t a_base_off = OFF_A + (uint32_t)(warp_m * 32 + a_row_local) * 128;
    const uint32_t b_base_off = OFF_B + (uint32_t)(warp_n * 64 + b_row_local) * 128;

    float acc[2][8][4];
#pragma unroll
    for (int i = 0; i < 2; ++i)
#pragma unroll
        for (int j = 0; j < 8; ++j)
#pragma unroll
            for (int k = 0; k < 4; ++k) acc[i][j][k] = 0.0f;

    int st = 0, ph = 0;
    for (int c = 0; c < KCHUNKS; ++c) {
        MBARRIER_WAIT_PARITY(sb + OFF_FULL(st), ph);
        const uint32_t base = sb + OFF_STAGE + st * STAGE_BYTES;

#pragma unroll
        for (int kk = 0; kk < BK / 16; ++kk) {
            // -------- all loads for this kk --------
            uint32_t af[2][4], bf[4][4];
            {
                const uint32_t koffA = (uint32_t)(kk * 32 + a_kadd) ^ ksw;
                ldsm_x4(af[0], base + a_base_off + koffA);
                ldsm_x4(af[1], base + a_base_off + 16 * 128 + koffA);
                const uint32_t koffB = (uint32_t)(kk * 32 + b_kadd) ^ ksw;
#pragma unroll
                for (int g = 0; g < 4; ++g)
                    ldsm_x4(bf[g], base + b_base_off + (uint32_t)(g * 16) * 128 + koffB);
            }
            // stage smem is dead for this warp after the last ldsm of kk==3
            if (kk == BK / 16 - 1) {
                __syncwarp();
                if (lane == 0) MBARRIER_ARRIVE(sb + OFF_EMPTY(st));
            }
            // -------- 16 MMAs --------
#pragma unroll
            for (int g = 0; g < 4; ++g) {
#pragma unroll
                for (int mt = 0; mt < 2; ++mt) {
                    mma16816(acc[mt][2 * g],     af[mt], bf[g]);
                    mma16816(acc[mt][2 * g + 1], af[mt], bf[g] + 2);
                }
            }
        }

        // rotating producer: warp (c & 7) refills stage st for chunk c+NSTAGES
        if (wid == (c & 7) && lane == 0 && c + NSTAGES < KCHUNKS) {
            MBARRIER_WAIT_PARITY(sb + OFF_EMPTY(st), ph);
            MBARRIER_EXPECT_TX(sb + OFF_FULL(st), STAGE_BYTES);
            const int k0 = (c + NSTAGES) * BK;
            TMA_LOAD_2D(base + OFF_A, &mapA, k0, m0, sb + OFF_FULL(st));
            TMA_LOAD_2D(base + OFF_B, &mapB, k0, n0, sb + OFF_FULL(st));
        }

        if (++st == NSTAGES) { st = 0; ph ^= 1; }
    }

    // ---------------- epilogue: bias + (scatter fp16 | fp32 store) ----------------
#pragma unroll
    for (int mt = 0; mt < 2; ++mt) {
        const size_t qa = (mt == 0) ? q0 : q2;
        const size_t qb = (mt == 0) ? q1 : q3;
#pragma unroll
        for (int nt = 0; nt < 8; ++nt) {
            const int cl = warp_n * 64 + nt * 8 + (lane & 3) * 2;
            const float b0 = bias_s[cl], b1 = bias_s[cl + 1];
            const float v0 = acc[mt][nt][0] + b0, v1 = acc[mt][nt][1] + b1;
            const float v2 = acc[mt][nt][2] + b0, v3 = acc[mt][nt][3] + b1;
            const size_t g0 = qa * HDIM + n0 + cl;
            const size_t g1 = qb * HDIM + n0 + cl;
            if (outF) {
                *(float2*)(outF + g0) = make_float2(v0, v1);
                *(float2*)(outF + g1) = make_float2(v2, v3);
            } else {
                __half2 p0 = __floats2half2_rn(v0, v1);
                __half2 p1 = __floats2half2_rn(v2, v3);
                *(__half2*)(outA + g0) = p0;
                *(__half2*)(outA + g1) = p1;
            }
        }
    }
}

// ---------------- host launcher ----------------
typedef CUresult (*EncodeFn)(CUtensorMap*, CUtensorMapDataType, cuuint32_t, void*,
                             const cuuint64_t*, const cuuint64_t*, const cuuint32_t*,
                             const cuuint32_t*, CUtensorMapInterleave, CUtensorMapSwizzle,
                             CUtensorMapL2promotion, CUtensorMapFloatOOBfill);

static void make_map(EncodeFn enc, CUtensorMap* m, void* base, uint64_t rows, uint32_t box_rows) {
    cuuint64_t dims[2]    = {(cuuint64_t)HDIM, (cuuint64_t)rows};
    cuuint64_t strides[1] = {(cuuint64_t)HDIM * 2};
    cuuint32_t box[2]     = {(cuuint32_t)BK, (cuuint32_t)box_rows};
    cuuint32_t es[2]      = {1, 1};
    enc(m, CU_TENSOR_MAP_DATA_TYPE_FLOAT16, 2, base, dims, strides, box, es,
        CU_TENSOR_MAP_INTERLEAVE_NONE, CU_TENSOR_MAP_SWIZZLE_128B,
        CU_TENSOR_MAP_L2_PROMOTION_L2_128B, CU_TENSOR_MAP_FLOAT_OOB_FILL_NONE);
}

extern "C" void kernel_launch(void* const* d_in, const int* in_sizes, int n_in,
                              void* d_out, int out_size)
{
    const float* x       = (const float*)d_in[0];
    const float* weights = (const float*)d_in[1];
    const float* biases  = (const float*)d_in[2];
    const int*   perms   = (const int*)  d_in[3];
    float*       out     = (float*)d_out;

    __half *act, *w;
    int* inv;
    cudaGetSymbolAddress((void**)&act, g_act);
    cudaGetSymbolAddress((void**)&w,   g_w);
    cudaGetSymbolAddress((void**)&inv, g_inv);

    EncodeFn enc = nullptr;
    cudaDriverEntryPointQueryResult st;
    cudaGetDriverEntryPointByVersion("cuTensorMapEncodeTiled", (void**)&enc, 12000,
                                     cudaEnableDefault, &st);

    cudaFuncSetAttribute(gemm_layer, cudaFuncAttributeMaxDynamicSharedMemorySize, SMEM_TOTAL);

    // pre-pass: x -> fp16, weights -> fp16, inverse perms
    {
        int n4x = (MTOT * HDIM) / 4;
        convert_f16_kernel<<<8192, 256>>>(x, act, n4x);
        int n4w = (NLAYER * HDIM * HDIM) / 4;
        convert_f16_kernel<<<8192, 256>>>(weights, w, n4w);
        invperm_kernel<<<((NLAYER - 1) * SEQ + 255) / 256, 256>>>(perms, inv);
    }

    const size_t ABUF = (size_t)MTOT * HDIM;
    const size_t WBUF = (size_t)HDIM * HDIM;
    const dim3 grid(HDIM / BN, MTOT / BM);   // (16, 256)

    for (int l = 0; l < NLAYER; ++l) {
        const int ib = l & 1;
        const int ob = ib ^ 1;
        CUtensorMap mA, mB;
        make_map(enc, &mA, act + (size_t)ib * ABUF, MTOT, BM);
        make_map(enc, &mB, w   + (size_t)l * WBUF, HDIM, BN);

        if (l < NLAYER - 1) {
            gemm_layer<<<grid, 256, SMEM_TOTAL>>>(
                mA, mB, biases + (size_t)l * HDIM,
                inv + (size_t)l * SEQ,
                act + (size_t)ob * ABUF, nullptr);
        } else {
            gemm_layer<<<grid, 256, SMEM_TOTAL>>>(
                mA, mB, biases + (size_t)l * HDIM,
                nullptr, nullptr, out);
        }
    }
}

// round 15
// speedup vs baseline: 1.0479x; 1.0479x over previous
#include <cuda_runtime.h>
#include <cuda_fp16.h>
#include <cuda.h>
#include <cstdint>

// ---------------- problem constants ----------------
#define HDIM   2048
#define SEQ    4096
#define NBATCH 8
#define MTOT   (NBATCH * SEQ)       // 32768
#define NLAYER 4

// ---------------- GEMM tile config ----------------
#define BM 128
#define BN 128
#define BK 64                        // 64 fp16 = 128 B rows (SW128)
#define KCHUNKS (HDIM / BK)          // 32
#define NSTAGES 3

// smem layout (bytes)
#define OFF_FULL(s)  ((s) * 8)       // 3 full barriers
#define OFF_EMPTY(s) (32 + (s) * 8)  // 3 empty barriers
#define OFF_BIAS     128             // BN floats = 512 B
#define OFF_STAGE    1024
#define OFF_A        0               // 128*128 B = 16384
#define OFF_B        16384           // 128*128 B = 16384
#define STAGE_BYTES  32768
#define SMEM_TOTAL   (OFF_STAGE + NSTAGES * STAGE_BYTES)   // 99328 -> 2 CTAs/SM

// ---------------- device scratch ----------------
__device__ __align__(1024) __half g_act[2ull * MTOT * HDIM];   // ping-pong fp16 activations
__device__ __align__(1024) __half g_w[(size_t)NLAYER * HDIM * HDIM];
__device__ int g_inv[(NLAYER - 1) * SEQ];

// ---------------- PTX helpers (baseline sm_103 only) ----------------
__device__ __forceinline__ uint32_t smem_u32(const void* p) {
    return (uint32_t)__cvta_generic_to_shared(p);
}

#define MBARRIER_INIT(addr, cnt) \
    asm volatile("mbarrier.init.shared.b64 [%0], %1;" :: "r"(addr), "r"(cnt) : "memory")

#define MBARRIER_ARRIVE(addr) \
    asm volatile("mbarrier.arrive.shared.b64 _, [%0];" :: "r"(addr) : "memory")

#define MBARRIER_EXPECT_TX(addr, bytes) \
    asm volatile("mbarrier.arrive.expect_tx.shared.b64 _, [%0], %1;" :: "r"(addr), "r"(bytes) : "memory")

#define MBARRIER_WAIT_PARITY(mbar_smem_addr, phase_parity) do { \
    uint32_t _mbar = (uint32_t)(mbar_smem_addr); \
    uint32_t _parity = (uint32_t)(phase_parity); \
    uint32_t _done_; \
    asm volatile( \
        "{\n\t.reg .pred p;\n\t" \
        "mbarrier.try_wait.parity.acquire.cta.shared::cta.b64 p, [%1], %2;\n\t" \
        "selp.b32 %0, 1, 0, p;\n\t}" \
        : "=r"(_done_) : "r"(_mbar), "r"(_parity) : "memory"); \
    if (!_done_) { \
        asm volatile( \
            "{\n\t.reg .pred P1;\n\t" \
            "WAIT_LOOP_%=:\n\t" \
            "mbarrier.try_wait.parity.acquire.cta.shared::cta.b64 P1, [%0], %1, 0x989680;\n\t" \
            "@P1 bra.uni WAIT_DONE_%=;\n\t" \
            "bra.uni WAIT_LOOP_%=;\n\t" \
            "WAIT_DONE_%=:\n\t}" \
            :: "r"(_mbar), "r"(_parity) : "memory"); \
    } \
} while (0)

#define TMA_LOAD_2D(dst, map, cx, cy, mbar) \
    asm volatile( \
        "cp.async.bulk.tensor.2d.shared::cta.global.tile.mbarrier::complete_tx::bytes " \
        "[%0], [%1, {%2, %3}], [%4];" \
        :: "r"((uint32_t)(dst)), "l"(map), "r"((int)(cx)), "r"((int)(cy)), "r"((uint32_t)(mbar)) \
        : "memory")

__device__ __forceinline__ void ldsm_x4(uint32_t* r, uint32_t addr) {
    asm volatile("ldmatrix.sync.aligned.m8n8.x4.shared.b16 {%0,%1,%2,%3}, [%4];"
        : "=r"(r[0]), "=r"(r[1]), "=r"(r[2]), "=r"(r[3]) : "r"(addr));
}

// D += A * B  (fp16 in, fp32 acc), m16n8k16
__device__ __forceinline__ void mma16816(float* d, const uint32_t* a, const uint32_t* b) {
    asm volatile("mma.sync.aligned.m16n8k16.row.col.f32.f16.f16.f32 "
        "{%0,%1,%2,%3}, {%4,%5,%6,%7}, {%8,%9}, {%0,%1,%2,%3};"
        : "+f"(d[0]), "+f"(d[1]), "+f"(d[2]), "+f"(d[3])
        : "r"(a[0]), "r"(a[1]), "r"(a[2]), "r"(a[3]), "r"(b[0]), "r"(b[1]));
}

// ---------------- pre-kernels ----------------
__global__ void convert_f16_kernel(const float* __restrict__ in,
                                   __half* __restrict__ out, int n4) {
    int stride = gridDim.x * blockDim.x;
    for (int i = blockIdx.x * blockDim.x + threadIdx.x; i < n4; i += stride) {
        float4 f = ((const float4*)in)[i];
        __half2 p0 = __floats2half2_rn(f.x, f.y);
        __half2 p1 = __floats2half2_rn(f.z, f.w);
        ((uint2*)out)[i] = make_uint2(*(uint32_t*)&p0, *(uint32_t*)&p1);
    }
}

__global__ void invperm_kernel(const int* __restrict__ perms, int* __restrict__ inv) {
    int i = blockIdx.x * blockDim.x + threadIdx.x;
    if (i < (NLAYER - 1) * SEQ) {
        int l = i / SEQ, s = i % SEQ;
        inv[l * SEQ + perms[i]] = s;
    }
}

// ---------------- main GEMM layer kernel ----------------
// C[BM x BN] = A_f16 . W_f16^T, +bias, scatter by invperm.
// 3-stage TMA pipeline; interleaved ldsm/MMA (round-13 proven structure);
// chunk loop unrolled in groups of NSTAGES so stage addressing constant-folds;
// producer duty rotates across the 8 warps; epilogue gather hoisted.
__global__ void __launch_bounds__(256, 2)
gemm_layer(const __grid_constant__ CUtensorMap mapA,
           const __grid_constant__ CUtensorMap mapB,
           const float* __restrict__ bias,
           const int* __restrict__ invperm,
           __half* __restrict__ outA,
           float* __restrict__ outF)
{
    extern __shared__ char smem[];
    const uint32_t sb = smem_u32(smem);
    const int tid  = threadIdx.x;
    const int wid  = tid >> 5;
    const int lane = tid & 31;
    const int warp_m = wid & 3;       // 4 warps along M (32 rows each)
    const int warp_n = wid >> 2;      // 2 warps along N (64 cols each)
    const int m0 = blockIdx.y * BM;
    const int n0 = blockIdx.x * BN;

    float* bias_s = (float*)(smem + OFF_BIAS);
    for (int i = tid; i < BN; i += 256) bias_s[i] = bias[n0 + i];

    if (tid == 0) {
#pragma unroll
        for (int s = 0; s < NSTAGES; ++s) {
            MBARRIER_INIT(sb + OFF_FULL(s), 1);
            MBARRIER_INIT(sb + OFF_EMPTY(s), 8);   // one arrival per warp
        }
    }
    __syncthreads();

    if (tid == 0) {
#pragma unroll
        for (int c = 0; c < NSTAGES; ++c) {
            MBARRIER_EXPECT_TX(sb + OFF_FULL(c), STAGE_BYTES);
            const uint32_t base = sb + OFF_STAGE + c * STAGE_BYTES;
            const int k0 = c * BK;
            TMA_LOAD_2D(base + OFF_A, &mapA, k0, m0, sb + OFF_FULL(c));
            TMA_LOAD_2D(base + OFF_B, &mapB, k0, n0, sb + OFF_FULL(c));
        }
    }

    // hoisted epilogue row gather (hide LDG latency behind the GEMM)
    const int r0 = m0 + warp_m * 32 + (lane >> 2);     // mt=0 row
    const int r1 = r0 + 8;
    const int r2 = r0 + 16;                            // mt=1 row
    const int r3 = r0 + 24;
    size_t q0, q1, q2, q3;
    if (invperm) {
        q0 = (size_t)((r0 & ~(SEQ - 1)) | invperm[r0 & (SEQ - 1)]);
        q1 = (size_t)((r1 & ~(SEQ - 1)) | invperm[r1 & (SEQ - 1)]);
        q2 = (size_t)((r2 & ~(SEQ - 1)) | invperm[r2 & (SEQ - 1)]);
        q3 = (size_t)((r3 & ~(SEQ - 1)) | invperm[r3 & (SEQ - 1)]);
    } else { q0 = (size_t)r0; q1 = (size_t)r1; q2 = (size_t)r2; q3 = (size_t)r3; }

    // per-lane ldmatrix geometry (SW128, 128B rows: phys_k = k ^ ((row&7)*16))
    const int rin = lane & 7;
    const int t8  = lane >> 3;                       // 8x8 tile index 0..3
    const int a_row_local = ((t8 & 1) << 3) + rin;   // A: tiles 0/1 rows, 2/3 k+16
    const int a_kadd      = (t8 >> 1) << 4;
    const int b_row_local = ((t8 >> 1) << 3) + rin;  // B: tiles 0/1 k, 2/3 n+8
    const int b_kadd      = (t8 & 1) << 4;
    const uint32_t ksw    = (uint32_t)(rin << 4);

    // invariant parts of ldsm addresses
    const uint32_t a_base_off = OFF_A + (uint32_t)(warp_m * 32 + a_row_local) * 128;
    const uint32_t b_base_off = OFF_B + (uint32_t)(warp_n * 64 + b_row_local) * 128;

    float acc[2][8][4];
#pragma unroll
    for (int i = 0; i < 2; ++i)
#pragma unroll
        for (int j = 0; j < 8; ++j)
#pragma unroll
            for (int k = 0; k < 4; ++k) acc[i][j][k] = 0.0f;

    // One K-chunk on compile-time stage ST (constant-folds all stage addressing).
#define DO_CHUNK(ST) do {                                                        \
        MBARRIER_WAIT_PARITY(sb + OFF_FULL(ST), ph);                             \
        const uint32_t base = sb + OFF_STAGE + (ST) * STAGE_BYTES;               \
        _Pragma("unroll")                                                        \
        for (int kk = 0; kk < BK / 16; ++kk) {                                   \
            uint32_t af[2][4];                                                   \
            const uint32_t koffA = (uint32_t)(kk * 32 + a_kadd) ^ ksw;           \
            ldsm_x4(af[0], base + a_base_off + koffA);                           \
            ldsm_x4(af[1], base + a_base_off + 16 * 128 + koffA);                \
            const uint32_t koffB = (uint32_t)(kk * 32 + b_kadd) ^ ksw;           \
            _Pragma("unroll")                                                    \
            for (int g = 0; g < 4; ++g) {                                        \
                uint32_t bf[4];                                                  \
                ldsm_x4(bf, base + b_base_off + (uint32_t)(g * 16) * 128 + koffB);\
                mma16816(acc[0][2 * g],     af[0], bf);                          \
                mma16816(acc[0][2 * g + 1], af[0], bf + 2);                      \
                mma16816(acc[1][2 * g],     af[1], bf);                          \
                mma16816(acc[1][2 * g + 1], af[1], bf + 2);                      \
            }                                                                    \
        }                                                                        \
        __syncwarp();                                                            \
        if (lane == 0) MBARRIER_ARRIVE(sb + OFF_EMPTY(ST));                      \
        if (wid == (c & 7) && lane == 0 && c + NSTAGES < KCHUNKS) {              \
            MBARRIER_WAIT_PARITY(sb + OFF_EMPTY(ST), ph);                        \
            MBARRIER_EXPECT_TX(sb + OFF_FULL(ST), STAGE_BYTES);                  \
            const int k0 = (c + NSTAGES) * BK;                                   \
            TMA_LOAD_2D(base + OFF_A, &mapA, k0, m0, sb + OFF_FULL(ST));         \
            TMA_LOAD_2D(base + OFF_B, &mapB, k0, n0, sb + OFF_FULL(ST));         \
        }                                                                        \
        ++c;                                                                     \
    } while (0)

    {
        int c = 0, ph = 0;
#pragma unroll 1
        for (int grp = 0; grp < KCHUNKS / NSTAGES; ++grp) {   // 10 groups -> chunks 0..29
            DO_CHUNK(0);
            DO_CHUNK(1);
            DO_CHUNK(2);
            ph ^= 1;
        }
        // tail: chunks 30 (stage 0) and 31 (stage 1); ph toggled 10x -> 0. correct.
        DO_CHUNK(0);
        DO_CHUNK(1);
    }
#undef DO_CHUNK

    // ---------------- epilogue: bias + (scatter fp16 | fp32 store) ----------------
#pragma unroll
    for (int mt = 0; mt < 2; ++mt) {
        const size_t qa = (mt == 0) ? q0 : q2;
        const size_t qb = (mt == 0) ? q1 : q3;
#pragma unroll
        for (int nt = 0; nt < 8; ++nt) {
            const int cl = warp_n * 64 + nt * 8 + (lane & 3) * 2;
            const float b0 = bias_s[cl], b1 = bias_s[cl + 1];
            const float v0 = acc[mt][nt][0] + b0, v1 = acc[mt][nt][1] + b1;
            const float v2 = acc[mt][nt][2] + b0, v3 = acc[mt][nt][3] + b1;
            const size_t g0 = qa * HDIM + n0 + cl;
            const size_t g1 = qb * HDIM + n0 + cl;
            if (outF) {
                *(float2*)(outF + g0) = make_float2(v0, v1);
                *(float2*)(outF + g1) = make_float2(v2, v3);
            } else {
                __half2 p0 = __floats2half2_rn(v0, v1);
                __half2 p1 = __floats2half2_rn(v2, v3);
                *(__half2*)(outA + g0) = p0;
                *(__half2*)(outA + g1) = p1;
            }
        }
    }
}

// ---------------- host launcher ----------------
typedef CUresult (*EncodeFn)(CUtensorMap*, CUtensorMapDataType, cuuint32_t, void*,
                             const cuuint64_t*, const cuuint64_t*, const cuuint32_t*,
                             const cuuint32_t*, CUtensorMapInterleave, CUtensorMapSwizzle,
                             CUtensorMapL2promotion, CUtensorMapFloatOOBfill);

static void make_map(EncodeFn enc, CUtensorMap* m, void* base, uint64_t rows, uint32_t box_rows) {
    cuuint64_t dims[2]    = {(cuuint64_t)HDIM, (cuuint64_t)rows};
    cuuint64_t strides[1] = {(cuuint64_t)HDIM * 2};
    cuuint32_t box[2]     = {(cuuint32_t)BK, (cuuint32_t)box_rows};
    cuuint32_t es[2]      = {1, 1};
    enc(m, CU_TENSOR_MAP_DATA_TYPE_FLOAT16, 2, base, dims, strides, box, es,
        CU_TENSOR_MAP_INTERLEAVE_NONE, CU_TENSOR_MAP_SWIZZLE_128B,
        CU_TENSOR_MAP_L2_PROMOTION_L2_128B, CU_TENSOR_MAP_FLOAT_OOB_FILL_NONE);
}

extern "C" void kernel_launch(void* const* d_in, const int* in_sizes, int n_in,
                              void* d_out, int out_size)
{
    const float* x       = (const float*)d_in[0];
    const float* weights = (const float*)d_in[1];
    const float* biases  = (const float*)d_in[2];
    const int*   perms   = (const int*)  d_in[3];
    float*       out     = (float*)d_out;

    __half *act, *w;
    int* inv;
    cudaGetSymbolAddress((void**)&act, g_act);
    cudaGetSymbolAddress((void**)&w,   g_w);
    cudaGetSymbolAddress((void**)&inv, g_inv);

    EncodeFn enc = nullptr;
    cudaDriverEntryPointQueryResult st;
    cudaGetDriverEntryPointByVersion("cuTensorMapEncodeTiled", (void**)&enc, 12000,
                                     cudaEnableDefault, &st);

    cudaFuncSetAttribute(gemm_layer, cudaFuncAttributeMaxDynamicSharedMemorySize, SMEM_TOTAL);

    // pre-pass: x -> fp16, weights -> fp16, inverse perms
    {
        int n4x = (MTOT * HDIM) / 4;
        convert_f16_kernel<<<8192, 256>>>(x, act, n4x);
        int n4w = (NLAYER * HDIM * HDIM) / 4;
        convert_f16_kernel<<<8192, 256>>>(weights, w, n4w);
        invperm_kernel<<<((NLAYER - 1) * SEQ + 255) / 256, 256>>>(perms, inv);
    }

    const size_t ABUF = (size_t)MTOT * HDIM;
    const size_t WBUF = (size_t)HDIM * HDIM;
    const dim3 grid(HDIM / BN, MTOT / BM);   // (16, 256)

    for (int l = 0; l < NLAYER; ++l) {
        const int ib = l & 1;
        const int ob = ib ^ 1;
        CUtensorMap mA, mB;
        make_map(enc, &mA, act + (size_t)ib * ABUF, MTOT, BM);
        make_map(enc, &mB, w   + (size_t)l * WBUF, HDIM, BN);

        if (l < NLAYER - 1) {
            gemm_layer<<<grid, 256, SMEM_TOTAL>>>(
                mA, mB, biases + (size_t)l * HDIM,
                inv + (size_t)l * SEQ,
                act + (size_t)ob * ABUF, nullptr);
        } else {
            gemm_layer<<<grid, 256, SMEM_TOTAL>>>(
                mA, mB, biases + (size_t)l * HDIM,
                nullptr, nullptr, out);
        }
    }
}

// round 16
// speedup vs baseline: 1.0516x; 1.0035x over previous
#include <cuda_runtime.h>
#include <cuda_fp16.h>
#include <cuda.h>
#include <cstdint>

// ---------------- problem constants ----------------
#define HDIM   2048
#define SEQ    4096
#define NBATCH 8
#define MTOT   (NBATCH * SEQ)       // 32768
#define NLAYER 4

// ---------------- GEMM tile config ----------------
#define BM 128
#define BN 128
#define BK 64                        // 64 fp16 = 128 B rows (SW128)
#define KCHUNKS (HDIM / BK)          // 32
#define NSTAGES 3

// smem layout (bytes)
#define OFF_FULL(s)  ((s) * 8)       // 3 full barriers
#define OFF_EMPTY(s) (32 + (s) * 8)  // 3 empty barriers
#define OFF_BIAS     128             // BN floats = 512 B
#define OFF_STAGE    1024
#define OFF_A        0               // 128*128 B = 16384
#define OFF_B        16384           // 128*128 B = 16384
#define STAGE_BYTES  32768
#define SMEM_TOTAL   (OFF_STAGE + NSTAGES * STAGE_BYTES)   // 99328 -> 2 CTAs/SM

// ---------------- device scratch ----------------
__device__ __align__(1024) __half g_act[2ull * MTOT * HDIM];   // ping-pong fp16 activations
__device__ __align__(1024) __half g_w[(size_t)NLAYER * HDIM * HDIM];
__device__ int g_inv[(NLAYER - 1) * SEQ];

// ---------------- PTX helpers (baseline sm_103 only) ----------------
__device__ __forceinline__ uint32_t smem_u32(const void* p) {
    return (uint32_t)__cvta_generic_to_shared(p);
}

#define MBARRIER_INIT(addr, cnt) \
    asm volatile("mbarrier.init.shared.b64 [%0], %1;" :: "r"(addr), "r"(cnt) : "memory")

#define MBARRIER_ARRIVE(addr) \
    asm volatile("mbarrier.arrive.shared.b64 _, [%0];" :: "r"(addr) : "memory")

#define MBARRIER_EXPECT_TX(addr, bytes) \
    asm volatile("mbarrier.arrive.expect_tx.shared.b64 _, [%0], %1;" :: "r"(addr), "r"(bytes) : "memory")

#define MBARRIER_WAIT_PARITY(mbar_smem_addr, phase_parity) do { \
    uint32_t _mbar = (uint32_t)(mbar_smem_addr); \
    uint32_t _parity = (uint32_t)(phase_parity); \
    uint32_t _done_; \
    asm volatile( \
        "{\n\t.reg .pred p;\n\t" \
        "mbarrier.try_wait.parity.acquire.cta.shared::cta.b64 p, [%1], %2;\n\t" \
        "selp.b32 %0, 1, 0, p;\n\t}" \
        : "=r"(_done_) : "r"(_mbar), "r"(_parity) : "memory"); \
    if (!_done_) { \
        asm volatile( \
            "{\n\t.reg .pred P1;\n\t" \
            "WAIT_LOOP_%=:\n\t" \
            "mbarrier.try_wait.parity.acquire.cta.shared::cta.b64 P1, [%0], %1, 0x989680;\n\t" \
            "@P1 bra.uni WAIT_DONE_%=;\n\t" \
            "bra.uni WAIT_LOOP_%=;\n\t" \
            "WAIT_DONE_%=:\n\t}" \
            :: "r"(_mbar), "r"(_parity) : "memory"); \
    } \
} while (0)

#define TMA_LOAD_2D(dst, map, cx, cy, mbar) \
    asm volatile( \
        "cp.async.bulk.tensor.2d.shared::cta.global.tile.mbarrier::complete_tx::bytes " \
        "[%0], [%1, {%2, %3}], [%4];" \
        :: "r"((uint32_t)(dst)), "l"(map), "r"((int)(cx)), "r"((int)(cy)), "r"((uint32_t)(mbar)) \
        : "memory")

__device__ __forceinline__ void ldsm_x4(uint32_t* r, uint32_t addr) {
    asm volatile("ldmatrix.sync.aligned.m8n8.x4.shared.b16 {%0,%1,%2,%3}, [%4];"
        : "=r"(r[0]), "=r"(r[1]), "=r"(r[2]), "=r"(r[3]) : "r"(addr));
}

// D += A * B  (fp16 in, fp32 acc), m16n8k16
__device__ __forceinline__ void mma16816(float* d, const uint32_t* a, const uint32_t* b) {
    asm volatile("mma.sync.aligned.m16n8k16.row.col.f32.f16.f16.f32 "
        "{%0,%1,%2,%3}, {%4,%5,%6,%7}, {%8,%9}, {%0,%1,%2,%3};"
        : "+f"(d[0]), "+f"(d[1]), "+f"(d[2]), "+f"(d[3])
        : "r"(a[0]), "r"(a[1]), "r"(a[2]), "r"(a[3]), "r"(b[0]), "r"(b[1]));
}

// ---------------- pre-kernels ----------------
__global__ void convert_f16_kernel(const float* __restrict__ in,
                                   __half* __restrict__ out, int n4) {
    int stride = gridDim.x * blockDim.x;
    for (int i = blockIdx.x * blockDim.x + threadIdx.x; i < n4; i += stride) {
        float4 f = ((const float4*)in)[i];
        __half2 p0 = __floats2half2_rn(f.x, f.y);
        __half2 p1 = __floats2half2_rn(f.z, f.w);
        ((uint2*)out)[i] = make_uint2(*(uint32_t*)&p0, *(uint32_t*)&p1);
    }
}

__global__ void invperm_kernel(const int* __restrict__ perms, int* __restrict__ inv) {
    int i = blockIdx.x * blockDim.x + threadIdx.x;
    if (i < (NLAYER - 1) * SEQ) {
        int l = i / SEQ, s = i % SEQ;
        inv[l * SEQ + perms[i]] = s;
    }
}

// ---------------- main GEMM layer kernel ----------------
// C[BM x BN] = A_f16 . W_f16^T, +bias, scatter by invperm.
// 3-stage TMA pipeline; interleaved ldsm/MMA (round-13 proven structure);
// chunk loop unrolled in groups of NSTAGES so stage addressing constant-folds;
// producer duty rotates across the 8 warps; epilogue gather hoisted.
__global__ void __launch_bounds__(256, 2)
gemm_layer(const __grid_constant__ CUtensorMap mapA,
           const __grid_constant__ CUtensorMap mapB,
           const float* __restrict__ bias,
           const int* __restrict__ invperm,
           __half* __restrict__ outA,
           float* __restrict__ outF)
{
    extern __shared__ char smem[];
    const uint32_t sb = smem_u32(smem);
    const int tid  = threadIdx.x;
    const int wid  = tid >> 5;
    const int lane = tid & 31;
    const int warp_m = wid & 3;       // 4 warps along M (32 rows each)
    const int warp_n = wid >> 2;      // 2 warps along N (64 cols each)
    const int m0 = blockIdx.y * BM;
    const int n0 = blockIdx.x * BN;

    float* bias_s = (float*)(smem + OFF_BIAS);
    for (int i = tid; i < BN; i += 256) bias_s[i] = bias[n0 + i];

    if (tid == 0) {
#pragma unroll
        for (int s = 0; s < NSTAGES; ++s) {
            MBARRIER_INIT(sb + OFF_FULL(s), 1);
            MBARRIER_INIT(sb + OFF_EMPTY(s), 8);   // one arrival per warp
        }
    }
    __syncthreads();

    if (tid == 0) {
#pragma unroll
        for (int c = 0; c < NSTAGES; ++c) {
            MBARRIER_EXPECT_TX(sb + OFF_FULL(c), STAGE_BYTES);
            const uint32_t base = sb + OFF_STAGE + c * STAGE_BYTES;
            const int k0 = c * BK;
            TMA_LOAD_2D(base + OFF_A, &mapA, k0, m0, sb + OFF_FULL(c));
            TMA_LOAD_2D(base + OFF_B, &mapB, k0, n0, sb + OFF_FULL(c));
        }
    }

    // hoisted epilogue row gather (hide LDG latency behind the GEMM)
    const int r0 = m0 + warp_m * 32 + (lane >> 2);     // mt=0 row
    const int r1 = r0 + 8;
    const int r2 = r0 + 16;                            // mt=1 row
    const int r3 = r0 + 24;
    size_t q0, q1, q2, q3;
    if (invperm) {
        q0 = (size_t)((r0 & ~(SEQ - 1)) | invperm[r0 & (SEQ - 1)]);
        q1 = (size_t)((r1 & ~(SEQ - 1)) | invperm[r1 & (SEQ - 1)]);
        q2 = (size_t)((r2 & ~(SEQ - 1)) | invperm[r2 & (SEQ - 1)]);
        q3 = (size_t)((r3 & ~(SEQ - 1)) | invperm[r3 & (SEQ - 1)]);
    } else { q0 = (size_t)r0; q1 = (size_t)r1; q2 = (size_t)r2; q3 = (size_t)r3; }

    // per-lane ldmatrix geometry (SW128, 128B rows: phys_k = k ^ ((row&7)*16))
    const int rin = lane & 7;
    const int t8  = lane >> 3;                       // 8x8 tile index 0..3
    const int a_row_local = ((t8 & 1) << 3) + rin;   // A: tiles 0/1 rows, 2/3 k+16
    const int a_kadd      = (t8 >> 1) << 4;
    const int b_row_local = ((t8 >> 1) << 3) + rin;  // B: tiles 0/1 k, 2/3 n+8
    const int b_kadd      = (t8 & 1) << 4;
    const uint32_t ksw    = (uint32_t)(rin << 4);

    // invariant parts of ldsm addresses
    const uint32_t a_base_off = OFF_A + (uint32_t)(warp_m * 32 + a_row_local) * 128;
    const uint32_t b_base_off = OFF_B + (uint32_t)(warp_n * 64 + b_row_local) * 128;

    float acc[2][8][4];
#pragma unroll
    for (int i = 0; i < 2; ++i)
#pragma unroll
        for (int j = 0; j < 8; ++j)
#pragma unroll
            for (int k = 0; k < 4; ++k) acc[i][j][k] = 0.0f;

    // One K-chunk on compile-time stage ST (constant-folds all stage addressing).
#define DO_CHUNK(ST) do {                                                        \
        MBARRIER_WAIT_PARITY(sb + OFF_FULL(ST), ph);                             \
        const uint32_t base = sb + OFF_STAGE + (ST) * STAGE_BYTES;               \
        _Pragma("unroll")                                                        \
        for (int kk = 0; kk < BK / 16; ++kk) {                                   \
            uint32_t af[2][4];                                                   \
            const uint32_t koffA = (uint32_t)(kk * 32 + a_kadd) ^ ksw;           \
            ldsm_x4(af[0], base + a_base_off + koffA);                           \
            ldsm_x4(af[1], base + a_base_off + 16 * 128 + koffA);                \
            const uint32_t koffB = (uint32_t)(kk * 32 + b_kadd) ^ ksw;           \
            _Pragma("unroll")                                                    \
            for (int g = 0; g < 4; ++g) {                                        \
                uint32_t bf[4];                                                  \
                ldsm_x4(bf, base + b_base_off + (uint32_t)(g * 16) * 128 + koffB);\
                mma16816(acc[0][2 * g],     af[0], bf);                          \
                mma16816(acc[0][2 * g + 1], af[0], bf + 2);                      \
                mma16816(acc[1][2 * g],     af[1], bf);                          \
                mma16816(acc[1][2 * g + 1], af[1], bf + 2);                      \
            }                                                                    \
        }                                                                        \
        __syncwarp();                                                            \
        if (lane == 0) MBARRIER_ARRIVE(sb + OFF_EMPTY(ST));                      \
        if (wid == (c & 7) && lane == 0 && c + NSTAGES < KCHUNKS) {              \
            MBARRIER_WAIT_PARITY(sb + OFF_EMPTY(ST), ph);                        \
            MBARRIER_EXPECT_TX(sb + OFF_FULL(ST), STAGE_BYTES);                  \
            const int k0 = (c + NSTAGES) * BK;                                   \
            TMA_LOAD_2D(base + OFF_A, &mapA, k0, m0, sb + OFF_FULL(ST));         \
            TMA_LOAD_2D(base + OFF_B, &mapB, k0, n0, sb + OFF_FULL(ST));         \
        }                                                                        \
        ++c;                                                                     \
    } while (0)

    {
        int c = 0, ph = 0;
#pragma unroll 1
        for (int grp = 0; grp < KCHUNKS / NSTAGES; ++grp) {   // 10 groups -> chunks 0..29
            DO_CHUNK(0);
            DO_CHUNK(1);
            DO_CHUNK(2);
            ph ^= 1;
        }
        // tail: chunks 30 (stage 0) and 31 (stage 1); ph toggled 10x -> 0. correct.
        DO_CHUNK(0);
        DO_CHUNK(1);
    }
#undef DO_CHUNK

    // ---------------- epilogue: bias + (scatter fp16 | fp32 store) ----------------
#pragma unroll
    for (int mt = 0; mt < 2; ++mt) {
        const size_t qa = (mt == 0) ? q0 : q2;
        const size_t qb = (mt == 0) ? q1 : q3;
#pragma unroll
        for (int nt = 0; nt < 8; ++nt) {
            const int cl = warp_n * 64 + nt * 8 + (lane & 3) * 2;
            const float b0 = bias_s[cl], b1 = bias_s[cl + 1];
            const float v0 = acc[mt][nt][0] + b0, v1 = acc[mt][nt][1] + b1;
            const float v2 = acc[mt][nt][2] + b0, v3 = acc[mt][nt][3] + b1;
            const size_t g0 = qa * HDIM + n0 + cl;
            const size_t g1 = qb * HDIM + n0 + cl;
            if (outF) {
                *(float2*)(outF + g0) = make_float2(v0, v1);
                *(float2*)(outF + g1) = make_float2(v2, v3);
            } else {
                __half2 p0 = __floats2half2_rn(v0, v1);
                __half2 p1 = __floats2half2_rn(v2, v3);
                *(__half2*)(outA + g0) = p0;
                *(__half2*)(outA + g1) = p1;
            }
        }
    }
}

// ---------------- host launcher ----------------
typedef CUresult (*EncodeFn)(CUtensorMap*, CUtensorMapDataType, cuuint32_t, void*,
                             const cuuint64_t*, const cuuint64_t*, const cuuint32_t*,
                             const cuuint32_t*, CUtensorMapInterleave, CUtensorMapSwizzle,
                             CUtensorMapL2promotion, CUtensorMapFloatOOBfill);

static void make_map(EncodeFn enc, CUtensorMap* m, void* base, uint64_t rows, uint32_t box_rows) {
    cuuint64_t dims[2]    = {(cuuint64_t)HDIM, (cuuint64_t)rows};
    cuuint64_t strides[1] = {(cuuint64_t)HDIM * 2};
    cuuint32_t box[2]     = {(cuuint32_t)BK, (cuuint32_t)box_rows};
    cuuint32_t es[2]      = {1, 1};
    enc(m, CU_TENSOR_MAP_DATA_TYPE_FLOAT16, 2, base, dims, strides, box, es,
        CU_TENSOR_MAP_INTERLEAVE_NONE, CU_TENSOR_MAP_SWIZZLE_128B,
        CU_TENSOR_MAP_L2_PROMOTION_L2_128B, CU_TENSOR_MAP_FLOAT_OOB_FILL_NONE);
}

extern "C" void kernel_launch(void* const* d_in, const int* in_sizes, int n_in,
                              void* d_out, int out_size)
{
    const float* x       = (const float*)d_in[0];
    const float* weights = (const float*)d_in[1];
    const float* biases  = (const float*)d_in[2];
    const int*   perms   = (const int*)  d_in[3];
    float*       out     = (float*)d_out;

    __half *act, *w;
    int* inv;
    cudaGetSymbolAddress((void**)&act, g_act);
    cudaGetSymbolAddress((void**)&w,   g_w);
    cudaGetSymbolAddress((void**)&inv, g_inv);

    EncodeFn enc = nullptr;
    cudaDriverEntryPointQueryResult st;
    cudaGetDriverEntryPointByVersion("cuTensorMapEncodeTiled", (void**)&enc, 12000,
                                     cudaEnableDefault, &st);

    cudaFuncSetAttribute(gemm_layer, cudaFuncAttributeMaxDynamicSharedMemorySize, SMEM_TOTAL);

    // pre-pass: x -> fp16, weights -> fp16, inverse perms
    {
        int n4x = (MTOT * HDIM) / 4;
        convert_f16_kernel<<<8192, 256>>>(x, act, n4x);
        int n4w = (NLAYER * HDIM * HDIM) / 4;
        convert_f16_kernel<<<8192, 256>>>(weights, w, n4w);
        invperm_kernel<<<((NLAYER - 1) * SEQ + 255) / 256, 256>>>(perms, inv);
    }

    const size_t ABUF = (size_t)MTOT * HDIM;
    const size_t WBUF = (size_t)HDIM * HDIM;
    const dim3 grid(HDIM / BN, MTOT / BM);   // (16, 256)

    for (int l = 0; l < NLAYER; ++l) {
        const int ib = l & 1;
        const int ob = ib ^ 1;
        CUtensorMap mA, mB;
        make_map(enc, &mA, act + (size_t)ib * ABUF, MTOT, BM);
        make_map(enc, &mB, w   + (size_t)l * WBUF, HDIM, BN);

        if (l < NLAYER - 1) {
            gemm_layer<<<grid, 256, SMEM_TOTAL>>>(
                mA, mB, biases + (size_t)l * HDIM,
                inv + (size_t)l * SEQ,
                act + (size_t)ob * ABUF, nullptr);
        } else {
            gemm_layer<<<grid, 256, SMEM_TOTAL>>>(
                mA, mB, biases + (size_t)l * HDIM,
                nullptr, nullptr, out);
        }
    }
}

// round 17
// speedup vs baseline: 1.0521x; 1.0005x over previous
#include <cuda_runtime.h>
#include <cuda_fp16.h>
#include <cuda.h>
#include <cstdint>

// ---------------- problem constants ----------------
#define HDIM   2048
#define SEQ    4096
#define NBATCH 8
#define MTOT   (NBATCH * SEQ)       // 32768
#define NLAYER 4

// ---------------- GEMM tile config ----------------
#define BM 128
#define BN 128
#define BK 64                        // 64 fp16 = 128 B rows (SW128)
#define KCHUNKS (HDIM / BK)          // 32
#define NSTAGES 3

// smem layout (bytes)
#define OFF_FULL(s)  ((s) * 8)       // 3 full barriers
#define OFF_EMPTY(s) (32 + (s) * 8)  // 3 empty barriers
#define OFF_BIAS     128             // BN floats = 512 B
#define OFF_STAGE    1024
#define OFF_A        0               // 128*128 B = 16384
#define OFF_B        16384           // 128*128 B = 16384
#define STAGE_BYTES  32768
#define SMEM_TOTAL   (OFF_STAGE + NSTAGES * STAGE_BYTES)   // 99328 -> 2 CTAs/SM

// ---------------- device scratch ----------------
__device__ __align__(1024) __half g_act[2ull * MTOT * HDIM];   // ping-pong fp16 activations
__device__ __align__(1024) __half g_w[(size_t)NLAYER * HDIM * HDIM];
__device__ int g_inv[(NLAYER - 1) * SEQ];

// ---------------- PTX helpers (baseline sm_103 only) ----------------
__device__ __forceinline__ uint32_t smem_u32(const void* p) {
    return (uint32_t)__cvta_generic_to_shared(p);
}

#define MBARRIER_INIT(addr, cnt) \
    asm volatile("mbarrier.init.shared.b64 [%0], %1;" :: "r"(addr), "r"(cnt) : "memory")

#define MBARRIER_ARRIVE(addr) \
    asm volatile("mbarrier.arrive.shared.b64 _, [%0];" :: "r"(addr) : "memory")

#define MBARRIER_EXPECT_TX(addr, bytes) \
    asm volatile("mbarrier.arrive.expect_tx.shared.b64 _, [%0], %1;" :: "r"(addr), "r"(bytes) : "memory")

#define MBARRIER_WAIT_PARITY(mbar_smem_addr, phase_parity) do { \
    uint32_t _mbar = (uint32_t)(mbar_smem_addr); \
    uint32_t _parity = (uint32_t)(phase_parity); \
    uint32_t _done_; \
    asm volatile( \
        "{\n\t.reg .pred p;\n\t" \
        "mbarrier.try_wait.parity.acquire.cta.shared::cta.b64 p, [%1], %2;\n\t" \
        "selp.b32 %0, 1, 0, p;\n\t}" \
        : "=r"(_done_) : "r"(_mbar), "r"(_parity) : "memory"); \
    if (!_done_) { \
        asm volatile( \
            "{\n\t.reg .pred P1;\n\t" \
            "WAIT_LOOP_%=:\n\t" \
            "mbarrier.try_wait.parity.acquire.cta.shared::cta.b64 P1, [%0], %1, 0x989680;\n\t" \
            "@P1 bra.uni WAIT_DONE_%=;\n\t" \
            "bra.uni WAIT_LOOP_%=;\n\t" \
            "WAIT_DONE_%=:\n\t}" \
            :: "r"(_mbar), "r"(_parity) : "memory"); \
    } \
} while (0)

#define TMA_LOAD_2D(dst, map, cx, cy, mbar) \
    asm volatile( \
        "cp.async.bulk.tensor.2d.shared::cta.global.tile.mbarrier::complete_tx::bytes " \
        "[%0], [%1, {%2, %3}], [%4];" \
        :: "r"((uint32_t)(dst)), "l"(map), "r"((int)(cx)), "r"((int)(cy)), "r"((uint32_t)(mbar)) \
        : "memory")

__device__ __forceinline__ void ldsm_x4(uint32_t* r, uint32_t addr) {
    asm volatile("ldmatrix.sync.aligned.m8n8.x4.shared.b16 {%0,%1,%2,%3}, [%4];"
        : "=r"(r[0]), "=r"(r[1]), "=r"(r[2]), "=r"(r[3]) : "r"(addr));
}

// D += A * B  (fp16 in, fp32 acc), m16n8k16
__device__ __forceinline__ void mma16816(float* d, const uint32_t* a, const uint32_t* b) {
    asm volatile("mma.sync.aligned.m16n8k16.row.col.f32.f16.f16.f32 "
        "{%0,%1,%2,%3}, {%4,%5,%6,%7}, {%8,%9}, {%0,%1,%2,%3};"
        : "+f"(d[0]), "+f"(d[1]), "+f"(d[2]), "+f"(d[3])
        : "r"(a[0]), "r"(a[1]), "r"(a[2]), "r"(a[3]), "r"(b[0]), "r"(b[1]));
}

// ---------------- pre-kernels ----------------
__global__ void convert_f16_kernel(const float* __restrict__ in,
                                   __half* __restrict__ out, int n4) {
    int stride = gridDim.x * blockDim.x;
    for (int i = blockIdx.x * blockDim.x + threadIdx.x; i < n4; i += stride) {
        float4 f = ((const float4*)in)[i];
        __half2 p0 = __floats2half2_rn(f.x, f.y);
        __half2 p1 = __floats2half2_rn(f.z, f.w);
        ((uint2*)out)[i] = make_uint2(*(uint32_t*)&p0, *(uint32_t*)&p1);
    }
}

__global__ void invperm_kernel(const int* __restrict__ perms, int* __restrict__ inv) {
    int i = blockIdx.x * blockDim.x + threadIdx.x;
    if (i < (NLAYER - 1) * SEQ) {
        int l = i / SEQ, s = i % SEQ;
        inv[l * SEQ + perms[i]] = s;
    }
}

// ---------------- main GEMM layer kernel ----------------
// C[BM x BN] = A_f16 . W_f16^T, +bias, scatter by invperm.
// 3-stage TMA pipeline; interleaved ldsm/MMA (round-13 proven structure);
// chunk loop unrolled in groups of NSTAGES so stage addressing constant-folds;
// producer duty rotates across the 8 warps; epilogue gather hoisted.
__global__ void __launch_bounds__(256, 2)
gemm_layer(const __grid_constant__ CUtensorMap mapA,
           const __grid_constant__ CUtensorMap mapB,
           const float* __restrict__ bias,
           const int* __restrict__ invperm,
           __half* __restrict__ outA,
           float* __restrict__ outF)
{
    extern __shared__ char smem[];
    const uint32_t sb = smem_u32(smem);
    const int tid  = threadIdx.x;
    const int wid  = tid >> 5;
    const int lane = tid & 31;
    const int warp_m = wid & 3;       // 4 warps along M (32 rows each)
    const int warp_n = wid >> 2;      // 2 warps along N (64 cols each)
    const int m0 = blockIdx.y * BM;
    const int n0 = blockIdx.x * BN;

    float* bias_s = (float*)(smem + OFF_BIAS);
    for (int i = tid; i < BN; i += 256) bias_s[i] = bias[n0 + i];

    if (tid == 0) {
#pragma unroll
        for (int s = 0; s < NSTAGES; ++s) {
            MBARRIER_INIT(sb + OFF_FULL(s), 1);
            MBARRIER_INIT(sb + OFF_EMPTY(s), 8);   // one arrival per warp
        }
    }
    __syncthreads();

    if (tid == 0) {
#pragma unroll
        for (int c = 0; c < NSTAGES; ++c) {
            MBARRIER_EXPECT_TX(sb + OFF_FULL(c), STAGE_BYTES);
            const uint32_t base = sb + OFF_STAGE + c * STAGE_BYTES;
            const int k0 = c * BK;
            TMA_LOAD_2D(base + OFF_A, &mapA, k0, m0, sb + OFF_FULL(c));
            TMA_LOAD_2D(base + OFF_B, &mapB, k0, n0, sb + OFF_FULL(c));
        }
    }

    // hoisted epilogue row gather (hide LDG latency behind the GEMM)
    const int r0 = m0 + warp_m * 32 + (lane >> 2);     // mt=0 row
    const int r1 = r0 + 8;
    const int r2 = r0 + 16;                            // mt=1 row
    const int r3 = r0 + 24;
    size_t q0, q1, q2, q3;
    if (invperm) {
        q0 = (size_t)((r0 & ~(SEQ - 1)) | invperm[r0 & (SEQ - 1)]);
        q1 = (size_t)((r1 & ~(SEQ - 1)) | invperm[r1 & (SEQ - 1)]);
        q2 = (size_t)((r2 & ~(SEQ - 1)) | invperm[r2 & (SEQ - 1)]);
        q3 = (size_t)((r3 & ~(SEQ - 1)) | invperm[r3 & (SEQ - 1)]);
    } else { q0 = (size_t)r0; q1 = (size_t)r1; q2 = (size_t)r2; q3 = (size_t)r3; }

    // per-lane ldmatrix geometry (SW128, 128B rows: phys_k = k ^ ((row&7)*16))
    const int rin = lane & 7;
    const int t8  = lane >> 3;                       // 8x8 tile index 0..3
    const int a_row_local = ((t8 & 1) << 3) + rin;   // A: tiles 0/1 rows, 2/3 k+16
    const int a_kadd      = (t8 >> 1) << 4;
    const int b_row_local = ((t8 >> 1) << 3) + rin;  // B: tiles 0/1 k, 2/3 n+8
    const int b_kadd      = (t8 & 1) << 4;
    const uint32_t ksw    = (uint32_t)(rin << 4);

    // invariant parts of ldsm addresses
    const uint32_t a_base_off = OFF_A + (uint32_t)(warp_m * 32 + a_row_local) * 128;
    const uint32_t b_base_off = OFF_B + (uint32_t)(warp_n * 64 + b_row_local) * 128;

    float acc[2][8][4];
#pragma unroll
    for (int i = 0; i < 2; ++i)
#pragma unroll
        for (int j = 0; j < 8; ++j)
#pragma unroll
            for (int k = 0; k < 4; ++k) acc[i][j][k] = 0.0f;

    // One K-chunk on compile-time stage ST (constant-folds all stage addressing).
#define DO_CHUNK(ST) do {                                                        \
        MBARRIER_WAIT_PARITY(sb + OFF_FULL(ST), ph);                             \
        const uint32_t base = sb + OFF_STAGE + (ST) * STAGE_BYTES;               \
        _Pragma("unroll")                                                        \
        for (int kk = 0; kk < BK / 16; ++kk) {                                   \
            uint32_t af[2][4];                                                   \
            const uint32_t koffA = (uint32_t)(kk * 32 + a_kadd) ^ ksw;           \
            ldsm_x4(af[0], base + a_base_off + koffA);                           \
            ldsm_x4(af[1], base + a_base_off + 16 * 128 + koffA);                \
            const uint32_t koffB = (uint32_t)(kk * 32 + b_kadd) ^ ksw;           \
            _Pragma("unroll")                                                    \
            for (int g = 0; g < 4; ++g) {                                        \
                uint32_t bf[4];                                                  \
                ldsm_x4(bf, base + b_base_off + (uint32_t)(g * 16) * 128 + koffB);\
                mma16816(acc[0][2 * g],     af[0], bf);                          \
                mma16816(acc[0][2 * g + 1], af[0], bf + 2);                      \
                mma16816(acc[1][2 * g],     af[1], bf);                          \
                mma16816(acc[1][2 * g + 1], af[1], bf + 2);                      \
            }                                                                    \
        }                                                                        \
        __syncwarp();                                                            \
        if (lane == 0) MBARRIER_ARRIVE(sb + OFF_EMPTY(ST));                      \
        if (wid == (c & 7) && lane == 0 && c + NSTAGES < KCHUNKS) {              \
            MBARRIER_WAIT_PARITY(sb + OFF_EMPTY(ST), ph);                        \
            MBARRIER_EXPECT_TX(sb + OFF_FULL(ST), STAGE_BYTES);                  \
            const int k0 = (c + NSTAGES) * BK;                                   \
            TMA_LOAD_2D(base + OFF_A, &mapA, k0, m0, sb + OFF_FULL(ST));         \
            TMA_LOAD_2D(base + OFF_B, &mapB, k0, n0, sb + OFF_FULL(ST));         \
        }                                                                        \
        ++c;                                                                     \
    } while (0)

    {
        int c = 0, ph = 0;
#pragma unroll 1
        for (int grp = 0; grp < KCHUNKS / NSTAGES; ++grp) {   // 10 groups -> chunks 0..29
            DO_CHUNK(0);
            DO_CHUNK(1);
            DO_CHUNK(2);
            ph ^= 1;
        }
        // tail: chunks 30 (stage 0) and 31 (stage 1); ph toggled 10x -> 0. correct.
        DO_CHUNK(0);
        DO_CHUNK(1);
    }
#undef DO_CHUNK

    // ---------------- epilogue: bias + (scatter fp16 | fp32 store) ----------------
#pragma unroll
    for (int mt = 0; mt < 2; ++mt) {
        const size_t qa = (mt == 0) ? q0 : q2;
        const size_t qb = (mt == 0) ? q1 : q3;
#pragma unroll
        for (int nt = 0; nt < 8; ++nt) {
            const int cl = warp_n * 64 + nt * 8 + (lane & 3) * 2;
            const float b0 = bias_s[cl], b1 = bias_s[cl + 1];
            const float v0 = acc[mt][nt][0] + b0, v1 = acc[mt][nt][1] + b1;
            const float v2 = acc[mt][nt][2] + b0, v3 = acc[mt][nt][3] + b1;
            const size_t g0 = qa * HDIM + n0 + cl;
            const size_t g1 = qb * HDIM + n0 + cl;
            if (outF) {
                *(float2*)(outF + g0) = make_float2(v0, v1);
                *(float2*)(outF + g1) = make_float2(v2, v3);
            } else {
                __half2 p0 = __floats2half2_rn(v0, v1);
                __half2 p1 = __floats2half2_rn(v2, v3);
                *(__half2*)(outA + g0) = p0;
                *(__half2*)(outA + g1) = p1;
            }
        }
    }
}

// ---------------- host launcher ----------------
typedef CUresult (*EncodeFn)(CUtensorMap*, CUtensorMapDataType, cuuint32_t, void*,
                             const cuuint64_t*, const cuuint64_t*, const cuuint32_t*,
                             const cuuint32_t*, CUtensorMapInterleave, CUtensorMapSwizzle,
                             CUtensorMapL2promotion, CUtensorMapFloatOOBfill);

static void make_map(EncodeFn enc, CUtensorMap* m, void* base, uint64_t rows, uint32_t box_rows) {
    cuuint64_t dims[2]    = {(cuuint64_t)HDIM, (cuuint64_t)rows};
    cuuint64_t strides[1] = {(cuuint64_t)HDIM * 2};
    cuuint32_t box[2]     = {(cuuint32_t)BK, (cuuint32_t)box_rows};
    cuuint32_t es[2]      = {1, 1};
    enc(m, CU_TENSOR_MAP_DATA_TYPE_FLOAT16, 2, base, dims, strides, box, es,
        CU_TENSOR_MAP_INTERLEAVE_NONE, CU_TENSOR_MAP_SWIZZLE_128B,
        CU_TENSOR_MAP_L2_PROMOTION_L2_128B, CU_TENSOR_MAP_FLOAT_OOB_FILL_NONE);
}

extern "C" void kernel_launch(void* const* d_in, const int* in_sizes, int n_in,
                              void* d_out, int out_size)
{
    const float* x       = (const float*)d_in[0];
    const float* weights = (const float*)d_in[1];
    const float* biases  = (const float*)d_in[2];
    const int*   perms   = (const int*)  d_in[3];
    float*       out     = (float*)d_out;

    __half *act, *w;
    int* inv;
    cudaGetSymbolAddress((void**)&act, g_act);
    cudaGetSymbolAddress((void**)&w,   g_w);
    cudaGetSymbolAddress((void**)&inv, g_inv);

    EncodeFn enc = nullptr;
    cudaDriverEntryPointQueryResult st;
    cudaGetDriverEntryPointByVersion("cuTensorMapEncodeTiled", (void**)&enc, 12000,
                                     cudaEnableDefault, &st);

    cudaFuncSetAttribute(gemm_layer, cudaFuncAttributeMaxDynamicSharedMemorySize, SMEM_TOTAL);

    // pre-pass: x -> fp16, weights -> fp16, inverse perms
    {
        int n4x = (MTOT * HDIM) / 4;
        convert_f16_kernel<<<8192, 256>>>(x, act, n4x);
        int n4w = (NLAYER * HDIM * HDIM) / 4;
        convert_f16_kernel<<<8192, 256>>>(weights, w, n4w);
        invperm_kernel<<<((NLAYER - 1) * SEQ + 255) / 256, 256>>>(perms, inv);
    }

    const size_t ABUF = (size_t)MTOT * HDIM;
    const size_t WBUF = (size_t)HDIM * HDIM;
    const dim3 grid(HDIM / BN, MTOT / BM);   // (16, 256)

    for (int l = 0; l < NLAYER; ++l) {
        const int ib = l & 1;
        const int ob = ib ^ 1;
        CUtensorMap mA, mB;
        make_map(enc, &mA, act + (size_t)ib * ABUF, MTOT, BM);
        make_map(enc, &mB, w   + (size_t)l * WBUF, HDIM, BN);

        if (l < NLAYER - 1) {
            gemm_layer<<<grid, 256, SMEM_TOTAL>>>(
                mA, mB, biases + (size_t)l * HDIM,
                inv + (size_t)l * SEQ,
                act + (size_t)ob * ABUF, nullptr);
        } else {
            gemm_layer<<<grid, 256, SMEM_TOTAL>>>(
                mA, mB, biases + (size_t)l * HDIM,
                nullptr, nullptr, out);
        }
    }
}